// round 7
// baseline (speedup 1.0000x reference)
#include <cuda_runtime.h>
#include <cuda_fp16.h>
#include <math_constants.h>
#include <limits.h>
#include <stdint.h>

#define NPTS 500000
#define BGR 64
#define DIN 64
#define DH 128
#define DO 128
#define TILE 128

// ---------------- device scratch ----------------
__device__ float g_cc[BGR][DH];
// fp16 weight fragments: [kchunk][ntile(16)][lane(32)] -> uint2 {b0,b1}
__device__ uint2 g_W1f[4 * 16 * 32];
__device__ uint2 g_W2f[8 * 16 * 32];

__device__ __forceinline__ void atomicMaxFloat(float* addr, float val) {
    if (val >= 0.0f) atomicMax((int*)addr, __float_as_int(val));
    else             atomicMin((unsigned int*)addr, __float_as_uint(val));
}

__device__ __forceinline__ uint32_t pk16(float a, float b) {
    __half2 t = __halves2half2(__float2half_rn(a), __float2half_rn(b));
    return *(uint32_t*)&t;
}

__device__ __forceinline__ void mma16816(float* c, const uint32_t* a, uint32_t b0, uint32_t b1) {
    asm volatile(
        "mma.sync.aligned.m16n8k16.row.col.f32.f16.f16.f32 "
        "{%0,%1,%2,%3}, {%4,%5,%6,%7}, {%8,%9}, {%0,%1,%2,%3};"
        : "+f"(c[0]), "+f"(c[1]), "+f"(c[2]), "+f"(c[3])
        : "r"(a[0]), "r"(a[1]), "r"(a[2]), "r"(a[3]), "r"(b0), "r"(b1));
}

// ---------------- k_prep: out init + weight fragment packing ----------------
__global__ void k_prep(const float* __restrict__ W1, const float* __restrict__ W2,
                       float* out, int out_size) {
    int i = blockIdx.x * blockDim.x + threadIdx.x;   // 4096 threads
    int lim = (BGR * DO < out_size) ? BGR * DO : out_size;
    for (int j = i; j < lim; j += 4096) out[j] = -CUDART_INF_F;

    if (i < 4 * 16 * 32) {   // W1x fragment: t(4), j(16), l(32)
        int l = i & 31, t = i >> 9;
        int n = 8 * ((i >> 5) & 15) + (l >> 2);
        int k0 = 16 * t + 2 * (l & 3);
        uint2 v;
        v.x = pk16(W1[(DIN + k0) * DH + n],     W1[(DIN + k0 + 1) * DH + n]);
        v.y = pk16(W1[(DIN + k0 + 8) * DH + n], W1[(DIN + k0 + 9) * DH + n]);
        g_W1f[i] = v;
    }
    if (i < 8 * 16 * 32) {   // W2 fragment: t(8), j(16), l(32)
        int l = i & 31, t = i >> 9;
        int n = 8 * ((i >> 5) & 15) + (l >> 2);
        int k0 = 16 * t + 2 * (l & 3);
        uint2 v;
        v.x = pk16(W2[k0 * DO + n],       W2[(k0 + 1) * DO + n]);
        v.y = pk16(W2[(k0 + 8) * DO + n], W2[(k0 + 9) * DO + n]);
        g_W2f[i] = v;
    }
}

// ---------------- k_graph: per-graph COM + argmin + c_g + small outputs ----
__global__ __launch_bounds__(256) void k_graph(
    const float* __restrict__ x, const float* __restrict__ pos,
    const int* __restrict__ batch, const float* __restrict__ lf,
    const float* __restrict__ W1, const float* __restrict__ b1,
    float* out, int out_size) {

    __shared__ int s_s, s_e;
    __shared__ float s_red[3][8];
    __shared__ float s_com[3];
    __shared__ unsigned long long s_best;
    __shared__ int s_idx;
    __shared__ float s_x[DIN];
    __shared__ float s_p[3];

    const int g = blockIdx.x;
    const int tid = threadIdx.x;
    const int wid = tid >> 5, l = tid & 31;

    if (tid == 0) {
        int lo = 0, hi = NPTS;
        while (lo < hi) { int m = (lo + hi) >> 1; if (batch[m] < g) lo = m + 1; else hi = m; }
        s_s = lo;
        hi = NPTS;
        while (lo < hi) { int m = (lo + hi) >> 1; if (batch[m] <= g) lo = m + 1; else hi = m; }
        s_e = lo;
        s_best = ~0ull;
    }
    __syncthreads();
    const int s = s_s, e = s_e;

    // ---- phase A: COM ----
    float sx = 0.f, sy = 0.f, sz = 0.f;
    for (int i = s + tid; i < e; i += 256) {
        sx += pos[3 * i]; sy += pos[3 * i + 1]; sz += pos[3 * i + 2];
    }
    #pragma unroll
    for (int d = 16; d >= 1; d >>= 1) {
        sx += __shfl_xor_sync(0xffffffffu, sx, d);
        sy += __shfl_xor_sync(0xffffffffu, sy, d);
        sz += __shfl_xor_sync(0xffffffffu, sz, d);
    }
    if (l == 0) { s_red[0][wid] = sx; s_red[1][wid] = sy; s_red[2][wid] = sz; }
    __syncthreads();
    if (tid < 3) {
        float t = 0.f;
        #pragma unroll
        for (int w = 0; w < 8; w++) t += s_red[tid][w];
        float cnt = (float)(e - s);
        s_com[tid] = t / fmaxf(cnt, 1.0f);
    }
    __syncthreads();

    // ---- phase B: argmin dist (first occurrence) ----
    {
        const float cx = s_com[0], cy = s_com[1], cz = s_com[2];
        unsigned long long best = ~0ull;
        for (int i = s + tid; i < e; i += 256) {
            float dx = pos[3 * i] - cx, dy = pos[3 * i + 1] - cy, dz = pos[3 * i + 2] - cz;
            float d = sqrtf(dx * dx + dy * dy + dz * dz);
            unsigned long long key = ((unsigned long long)__float_as_uint(d) << 32) | (unsigned)i;
            if (key < best) best = key;
        }
        atomicMin(&s_best, best);
    }
    __syncthreads();
    if (tid == 0)
        s_idx = (e > s) ? (int)(unsigned)(s_best & 0xffffffffu) : (NPTS - 1);
    __syncthreads();
    const int idx = s_idx;
    if (tid < DIN) s_x[tid] = x[(size_t)idx * DIN + tid];
    if (tid < 3) s_p[tid] = pos[3 * idx + tid];
    __syncthreads();

    // ---- phase C: c_g + small outputs ----
    if (tid < DH) {
        int j = tid;
        float c = b1[j];
        #pragma unroll 8
        for (int k = 0; k < DIN; k++)
            c += s_x[k] * (W1[k * DH + j] - W1[(DIN + k) * DH + j]);
        c -= s_p[0] * W1[(2 * DIN) * DH + j] + s_p[1] * W1[(2 * DIN + 1) * DH + j]
           + s_p[2] * W1[(2 * DIN + 2) * DH + j];
        g_cc[g][j] = c;
        if (j < 3)  { int o = BGR * DO + g * 3 + j;               if (o < out_size) out[o] = s_p[j]; }
        if (j == 0) { int o = BGR * DO + BGR * 3 + g;             if (o < out_size) out[o] = (float)g; }
        if (j < 9)  { int o = BGR * DO + BGR * 3 + BGR + g*9 + j; if (o < out_size) out[o] = lf[(size_t)idx * 9 + j]; }
    }
}

// ---------------- main fused mma.sync kernel (fp16 single-pass) ----------------
__global__ void __launch_bounds__(256, 2) k_main(
    const float* __restrict__ x, const float* __restrict__ pos,
    const int* __restrict__ batch, const float* __restrict__ W1,
    const float* __restrict__ b2, float* __restrict__ out) {

    __shared__ float wpx[128], wpy[128], wpz[128];
    __shared__ float cgs[128], b2s[128];
    __shared__ float px[128], py[128], pz[128];
    __shared__ float red[8 * 128];
    __shared__ int gbs[128];

    const int tid = threadIdx.x;
    const int wid = tid >> 5, l = tid & 31;
    const int row0 = blockIdx.x * TILE;

    if (tid < 128) {
        wpx[tid] = W1[(2 * DIN + 0) * DH + tid];
        wpy[tid] = W1[(2 * DIN + 1) * DH + tid];
        wpz[tid] = W1[(2 * DIN + 2) * DH + tid];
        b2s[tid] = b2[tid];
        int row = row0 + tid;
        if (row < NPTS) {
            px[tid] = pos[3 * row]; py[tid] = pos[3 * row + 1]; pz[tid] = pos[3 * row + 2];
            gbs[tid] = batch[row];
        } else {
            px[tid] = py[tid] = pz[tid] = 0.f;
            gbs[tid] = -1;
        }
    }
    __syncthreads();
    const int gu = gbs[0];
    const bool uni = (gu >= 0) && (gu == gbs[127]);
    if (tid < 128) cgs[tid] = (gu >= 0) ? g_cc[gu][tid] : 0.f;
    __syncthreads();

    const int rr0 = wid * 16 + (l >> 2);
    const int rr1 = rr0 + 8;
    const int r0 = row0 + rr0, r1 = row0 + rr1;
    const int m4 = 2 * (l & 3);

    // ---------- load x fragments once (fp16, kept resident) ----------
    uint32_t xh[4][4];
    #pragma unroll
    for (int t = 0; t < 4; t++) {
        const int kb = 16 * t + m4;
        float2 x00 = make_float2(0.f, 0.f), x01 = x00, x10 = x00, x11 = x00;
        if (r0 < NPTS) {
            x00 = *(const float2*)(x + (size_t)r0 * DIN + kb);
            x01 = *(const float2*)(x + (size_t)r0 * DIN + kb + 8);
        }
        if (r1 < NPTS) {
            x10 = *(const float2*)(x + (size_t)r1 * DIN + kb);
            x11 = *(const float2*)(x + (size_t)r1 * DIN + kb + 8);
        }
        xh[t][0] = pk16(x00.x, x00.y); xh[t][1] = pk16(x10.x, x10.y);
        xh[t][2] = pk16(x01.x, x01.y); xh[t][3] = pk16(x11.x, x11.y);
    }

    const float p0x = px[rr0], p0y = py[rr0], p0z = pz[rr0];
    const float p1x = px[rr1], p1y = py[rr1], p1z = pz[rr1];
    const int g0 = gbs[rr0], g1 = gbs[rr1];

    // ---------- phase 1: two 64-col halves ----------
    uint32_t ah[16][2];
    #pragma unroll
    for (int h = 0; h < 2; h++) {
        float acc1[8][4];
        #pragma unroll
        for (int j = 0; j < 8; j++)
            #pragma unroll
            for (int q = 0; q < 4; q++) acc1[j][q] = 0.f;

        #pragma unroll
        for (int t = 0; t < 4; t++) {
            const uint2* wf = g_W1f + (t * 16 + h * 8) * 32 + l;
            uint2 B[8];
            #pragma unroll
            for (int j = 0; j < 8; j++) B[j] = wf[j * 32];
            #pragma unroll
            for (int j = 0; j < 8; j++) mma16816(acc1[j], xh[t], B[j].x, B[j].y);
        }

        // epilogue 1: + pos*Wp + c_g, relu -> fp16 A-frags
        #pragma unroll
        for (int j = 0; j < 8; j++) {
            int jj = h * 8 + j;
            int c0 = 8 * jj + m4;
            float2 wx = *(float2*)&wpx[c0];
            float2 wy = *(float2*)&wpy[c0];
            float2 wz = *(float2*)&wpz[c0];
            float2 cv0, cv1;
            if (uni) {
                cv0 = *(float2*)&cgs[c0]; cv1 = cv0;
            } else {
                cv0 = (g0 >= 0) ? *(const float2*)&g_cc[g0][c0] : make_float2(0.f, 0.f);
                cv1 = (g1 >= 0) ? *(const float2*)&g_cc[g1][c0] : make_float2(0.f, 0.f);
            }
            float v0 = fmaxf(acc1[j][0] + p0x * wx.x + p0y * wy.x + p0z * wz.x + cv0.x, 0.f);
            float v1 = fmaxf(acc1[j][1] + p0x * wx.y + p0y * wy.y + p0z * wz.y + cv0.y, 0.f);
            float v2 = fmaxf(acc1[j][2] + p1x * wx.x + p1y * wy.x + p1z * wz.x + cv1.x, 0.f);
            float v3 = fmaxf(acc1[j][3] + p1x * wx.y + p1y * wy.y + p1z * wz.y + cv1.y, 0.f);
            ah[jj][0] = pk16(v0, v1); ah[jj][1] = pk16(v2, v3);
        }
    }

    // ---------- phase 2: two 64-col halves ----------
    #pragma unroll
    for (int h = 0; h < 2; h++) {
        float acc2[8][4];
        #pragma unroll
        for (int j = 0; j < 8; j++)
            #pragma unroll
            for (int q = 0; q < 4; q++) acc2[j][q] = 0.f;

        #pragma unroll
        for (int t = 0; t < 8; t++) {
            uint32_t A[4] = { ah[2 * t][0], ah[2 * t][1], ah[2 * t + 1][0], ah[2 * t + 1][1] };
            const uint2* wf = g_W2f + (t * 16 + h * 8) * 32 + l;
            uint2 B[8];
            #pragma unroll
            for (int j = 0; j < 8; j++) B[j] = wf[j * 32];
            #pragma unroll
            for (int j = 0; j < 8; j++) mma16816(acc2[j], A, B[j].x, B[j].y);
        }

        // epilogue 2
        if (uni) {
            #pragma unroll
            for (int j = 0; j < 8; j++) {
                int c0 = 8 * (h * 8 + j) + m4;
                float m0 = fmaxf(acc2[j][0], acc2[j][2]);
                float m1 = fmaxf(acc2[j][1], acc2[j][3]);
                #pragma unroll
                for (int d = 4; d < 32; d <<= 1) {
                    m0 = fmaxf(m0, __shfl_xor_sync(0xffffffffu, m0, d));
                    m1 = fmaxf(m1, __shfl_xor_sync(0xffffffffu, m1, d));
                }
                if (l < 4) {
                    red[wid * 128 + c0] = m0;
                    red[wid * 128 + c0 + 1] = m1;
                }
            }
        } else {
            #pragma unroll
            for (int j = 0; j < 8; j++) {
                int c0 = 8 * (h * 8 + j) + m4;
                if (g0 >= 0) {
                    atomicMaxFloat(&out[g0 * DO + c0],     acc2[j][0] + b2s[c0]);
                    atomicMaxFloat(&out[g0 * DO + c0 + 1], acc2[j][1] + b2s[c0 + 1]);
                }
                if (g1 >= 0) {
                    atomicMaxFloat(&out[g1 * DO + c0],     acc2[j][2] + b2s[c0]);
                    atomicMaxFloat(&out[g1 * DO + c0 + 1], acc2[j][3] + b2s[c0 + 1]);
                }
            }
        }
    }

    if (uni) {
        __syncthreads();
        if (tid < 128) {
            float m = red[tid];
            #pragma unroll
            for (int w = 1; w < 8; w++) m = fmaxf(m, red[w * 128 + tid]);
            atomicMaxFloat(&out[gu * DO + tid], m + b2s[tid]);
        }
    }
}

// ---------------- launch ----------------
extern "C" void kernel_launch(void* const* d_in, const int* in_sizes, int n_in,
                              void* d_out, int out_size) {
    const float* x     = (const float*)d_in[0];
    const float* pos   = (const float*)d_in[1];
    const int*   batch = (const int*)d_in[2];
    const float* lf    = (const float*)d_in[3];
    const float* W1    = (const float*)d_in[4];
    const float* b1    = (const float*)d_in[5];
    const float* W2    = (const float*)d_in[6];
    const float* b2    = (const float*)d_in[7];
    float* out = (float*)d_out;

    k_prep<<<16, 256>>>(W1, W2, out, out_size);
    k_graph<<<BGR, 256>>>(x, pos, batch, lf, W1, b1, out, out_size);
    int grid = (NPTS + TILE - 1) / TILE;
    k_main<<<grid, 256>>>(x, pos, batch, W1, b2, out);
}

// round 8
// speedup vs baseline: 1.0068x; 1.0068x over previous
#include <cuda_runtime.h>
#include <cuda_fp16.h>
#include <math_constants.h>
#include <limits.h>
#include <stdint.h>

#define NPTS 500000
#define BGR 64
#define DIN 64
#define DH 128
#define DO 128
#define TILE 128

// ---------------- device scratch ----------------
__device__ float g_cc[BGR][DH];
// fp16 weight fragments: [kchunk][ntile(16)][lane(32)] -> uint2 {b0,b1}
__device__ uint2 g_W1f[4 * 16 * 32];
__device__ uint2 g_W2f[8 * 16 * 32];

__device__ __forceinline__ void atomicMaxFloat(float* addr, float val) {
    if (val >= 0.0f) atomicMax((int*)addr, __float_as_int(val));
    else             atomicMin((unsigned int*)addr, __float_as_uint(val));
}

__device__ __forceinline__ uint32_t pk16(float a, float b) {
    __half2 t = __halves2half2(__float2half_rn(a), __float2half_rn(b));
    return *(uint32_t*)&t;
}

__device__ __forceinline__ void mma16816(float* c, const uint32_t* a, uint32_t b0, uint32_t b1) {
    asm volatile(
        "mma.sync.aligned.m16n8k16.row.col.f32.f16.f16.f32 "
        "{%0,%1,%2,%3}, {%4,%5,%6,%7}, {%8,%9}, {%0,%1,%2,%3};"
        : "+f"(c[0]), "+f"(c[1]), "+f"(c[2]), "+f"(c[3])
        : "r"(a[0]), "r"(a[1]), "r"(a[2]), "r"(a[3]), "r"(b0), "r"(b1));
}

// ---------------- k_graph: prep + per-graph COM/argmin/c_g/small outputs ----
__global__ __launch_bounds__(256) void k_graph(
    const float* __restrict__ x, const float* __restrict__ pos,
    const int* __restrict__ batch, const float* __restrict__ lf,
    const float* __restrict__ W1, const float* __restrict__ W2,
    const float* __restrict__ b1, float* out, int out_size) {

    const int g = blockIdx.x;
    const int tid = threadIdx.x;
    const int wid = tid >> 5, l = tid & 31;

    // ---- prep section (distributed across blocks, independent of graph work)
    {
        int i = g * 256 + tid;   // 16384 threads
        int lim = (BGR * DO < out_size) ? BGR * DO : out_size;
        if (i < lim) out[i] = -CUDART_INF_F;

        if (i < 4 * 16 * 32) {   // W1x fragment: t(4), j(16), l(32)
            int ll = i & 31, t = i >> 9;
            int n = 8 * ((i >> 5) & 15) + (ll >> 2);
            int k0 = 16 * t + 2 * (ll & 3);
            uint2 v;
            v.x = pk16(W1[(DIN + k0) * DH + n],     W1[(DIN + k0 + 1) * DH + n]);
            v.y = pk16(W1[(DIN + k0 + 8) * DH + n], W1[(DIN + k0 + 9) * DH + n]);
            g_W1f[i] = v;
        }
        if (i < 8 * 16 * 32) {   // W2 fragment: t(8), j(16), l(32)
            int ll = i & 31, t = i >> 9;
            int n = 8 * ((i >> 5) & 15) + (ll >> 2);
            int k0 = 16 * t + 2 * (ll & 3);
            uint2 v;
            v.x = pk16(W2[k0 * DO + n],       W2[(k0 + 1) * DO + n]);
            v.y = pk16(W2[(k0 + 8) * DO + n], W2[(k0 + 9) * DO + n]);
            g_W2f[i] = v;
        }
    }

    __shared__ int s_s, s_e;
    __shared__ float s_red[3][8];
    __shared__ float s_com[3];
    __shared__ unsigned long long s_best;
    __shared__ int s_idx;
    __shared__ float s_x[DIN];
    __shared__ float s_p[3];

    if (tid == 0) {
        int lo = 0, hi = NPTS;
        while (lo < hi) { int m = (lo + hi) >> 1; if (batch[m] < g) lo = m + 1; else hi = m; }
        s_s = lo;
        hi = NPTS;
        while (lo < hi) { int m = (lo + hi) >> 1; if (batch[m] <= g) lo = m + 1; else hi = m; }
        s_e = lo;
        s_best = ~0ull;
    }
    __syncthreads();
    const int s = s_s, e = s_e;

    // ---- phase A: COM ----
    float sx = 0.f, sy = 0.f, sz = 0.f;
    for (int i = s + tid; i < e; i += 256) {
        sx += pos[3 * i]; sy += pos[3 * i + 1]; sz += pos[3 * i + 2];
    }
    #pragma unroll
    for (int d = 16; d >= 1; d >>= 1) {
        sx += __shfl_xor_sync(0xffffffffu, sx, d);
        sy += __shfl_xor_sync(0xffffffffu, sy, d);
        sz += __shfl_xor_sync(0xffffffffu, sz, d);
    }
    if (l == 0) { s_red[0][wid] = sx; s_red[1][wid] = sy; s_red[2][wid] = sz; }
    __syncthreads();
    if (tid < 3) {
        float t = 0.f;
        #pragma unroll
        for (int w = 0; w < 8; w++) t += s_red[tid][w];
        float cnt = (float)(e - s);
        s_com[tid] = t / fmaxf(cnt, 1.0f);
    }
    __syncthreads();

    // ---- phase B: argmin dist (first occurrence) ----
    {
        const float cx = s_com[0], cy = s_com[1], cz = s_com[2];
        unsigned long long best = ~0ull;
        for (int i = s + tid; i < e; i += 256) {
            float dx = pos[3 * i] - cx, dy = pos[3 * i + 1] - cy, dz = pos[3 * i + 2] - cz;
            float d = sqrtf(dx * dx + dy * dy + dz * dz);
            unsigned long long key = ((unsigned long long)__float_as_uint(d) << 32) | (unsigned)i;
            if (key < best) best = key;
        }
        atomicMin(&s_best, best);
    }
    __syncthreads();
    if (tid == 0)
        s_idx = (e > s) ? (int)(unsigned)(s_best & 0xffffffffu) : (NPTS - 1);
    __syncthreads();
    const int idx = s_idx;
    if (tid < DIN) s_x[tid] = x[(size_t)idx * DIN + tid];
    if (tid < 3) s_p[tid] = pos[3 * idx + tid];
    __syncthreads();

    // ---- phase C: c_g + small outputs ----
    if (tid < DH) {
        int j = tid;
        float c = b1[j];
        #pragma unroll 8
        for (int k = 0; k < DIN; k++)
            c += s_x[k] * (W1[k * DH + j] - W1[(DIN + k) * DH + j]);
        c -= s_p[0] * W1[(2 * DIN) * DH + j] + s_p[1] * W1[(2 * DIN + 1) * DH + j]
           + s_p[2] * W1[(2 * DIN + 2) * DH + j];
        g_cc[g][j] = c;
        if (j < 3)  { int o = BGR * DO + g * 3 + j;               if (o < out_size) out[o] = s_p[j]; }
        if (j == 0) { int o = BGR * DO + BGR * 3 + g;             if (o < out_size) out[o] = (float)g; }
        if (j < 9)  { int o = BGR * DO + BGR * 3 + BGR + g*9 + j; if (o < out_size) out[o] = lf[(size_t)idx * 9 + j]; }
    }
}

// ---------------- main fused mma.sync kernel (affine term folded into GEMM) -
__global__ void __launch_bounds__(256, 2) k_main(
    const float* __restrict__ x, const float* __restrict__ pos,
    const int* __restrict__ batch, const float* __restrict__ W1,
    const float* __restrict__ b2, float* __restrict__ out) {

    __shared__ float wpx[128], wpy[128], wpz[128];
    __shared__ float cgs[128], b2s[128];
    __shared__ float px[128], py[128], pz[128];
    __shared__ float red[8 * 128];
    __shared__ int gbs[128];

    const int tid = threadIdx.x;
    const int wid = tid >> 5, l = tid & 31;
    const int row0 = blockIdx.x * TILE;

    if (tid < 128) {
        wpx[tid] = W1[(2 * DIN + 0) * DH + tid];
        wpy[tid] = W1[(2 * DIN + 1) * DH + tid];
        wpz[tid] = W1[(2 * DIN + 2) * DH + tid];
        b2s[tid] = b2[tid];
        int row = row0 + tid;
        if (row < NPTS) {
            px[tid] = pos[3 * row]; py[tid] = pos[3 * row + 1]; pz[tid] = pos[3 * row + 2];
            gbs[tid] = batch[row];
        } else {
            px[tid] = py[tid] = pz[tid] = 0.f;
            gbs[tid] = -1;
        }
    }
    __syncthreads();
    const int gu = gbs[0];
    const bool uni = (gu >= 0) && (gu == gbs[127]);
    if (tid < 128) cgs[tid] = (gu >= 0) ? g_cc[gu][tid] : 0.f;
    __syncthreads();

    const int rr0 = wid * 16 + (l >> 2);
    const int rr1 = rr0 + 8;
    const int r0 = row0 + rr0, r1 = row0 + rr1;
    const int m4 = 2 * (l & 3);

    // ---------- load x fragments once (fp16, kept resident) ----------
    uint32_t xh[4][4];
    #pragma unroll
    for (int t = 0; t < 4; t++) {
        const int kb = 16 * t + m4;
        float2 x00 = make_float2(0.f, 0.f), x01 = x00, x10 = x00, x11 = x00;
        if (r0 < NPTS) {
            x00 = *(const float2*)(x + (size_t)r0 * DIN + kb);
            x01 = *(const float2*)(x + (size_t)r0 * DIN + kb + 8);
        }
        if (r1 < NPTS) {
            x10 = *(const float2*)(x + (size_t)r1 * DIN + kb);
            x11 = *(const float2*)(x + (size_t)r1 * DIN + kb + 8);
        }
        xh[t][0] = pk16(x00.x, x00.y); xh[t][1] = pk16(x10.x, x10.y);
        xh[t][2] = pk16(x01.x, x01.y); xh[t][3] = pk16(x11.x, x11.y);
    }

    const float p0x = px[rr0], p0y = py[rr0], p0z = pz[rr0];
    const float p1x = px[rr1], p1y = py[rr1], p1z = pz[rr1];
    const int g0 = gbs[rr0], g1 = gbs[rr1];

    // ---------- chunk-4 A fragment: rows carry [pos.x, pos.y, pos.z, 1] ------
    uint32_t xp[4];
    {
        const int sel = l & 3;
        float a0 = 0.f, a1 = 0.f, c0 = 0.f, c1 = 0.f;
        if (sel == 0) { a0 = p0x; a1 = p0y; c0 = p1x; c1 = p1y; }
        else if (sel == 1) { a0 = p0z; a1 = 1.f; c0 = p1z; c1 = 1.f; }
        xp[0] = pk16(a0, a1);
        xp[1] = pk16(c0, c1);
        xp[2] = 0u; xp[3] = 0u;
    }
    // ---------- chunk-4 B fragments: [Wpx; Wpy; Wpz; c_g(uni)] --------------
    uint32_t bp[16];
    {
        const int sel = l & 3;
        const int c = (l >> 2);
        #pragma unroll
        for (int jj = 0; jj < 16; jj++) {
            int n = 8 * jj + c;
            float v0 = 0.f, v1 = 0.f;
            if (sel == 0) { v0 = wpx[n]; v1 = wpy[n]; }
            else if (sel == 1) { v0 = wpz[n]; v1 = uni ? cgs[n] : 0.f; }
            bp[jj] = pk16(v0, v1);
        }
    }

    // ---------- phase 1: two 64-col halves (K = 64 + affine chunk) ----------
    uint32_t ah[16][2];
    #pragma unroll
    for (int h = 0; h < 2; h++) {
        float acc1[8][4];
        #pragma unroll
        for (int j = 0; j < 8; j++)
            #pragma unroll
            for (int q = 0; q < 4; q++) acc1[j][q] = 0.f;

        #pragma unroll
        for (int t = 0; t < 4; t++) {
            const uint2* wf = g_W1f + (t * 16 + h * 8) * 32 + l;
            uint2 B[8];
            #pragma unroll
            for (int j = 0; j < 8; j++) B[j] = wf[j * 32];
            #pragma unroll
            for (int j = 0; j < 8; j++) mma16816(acc1[j], xh[t], B[j].x, B[j].y);
        }
        // affine chunk
        #pragma unroll
        for (int j = 0; j < 8; j++) mma16816(acc1[j], xp, bp[h * 8 + j], 0u);

        // epilogue 1: relu (+ per-row c_g for mixed tiles) -> fp16 A-frags
        #pragma unroll
        for (int j = 0; j < 8; j++) {
            int jj = h * 8 + j;
            float v0, v1, v2, v3;
            if (uni) {
                v0 = fmaxf(acc1[j][0], 0.f);
                v1 = fmaxf(acc1[j][1], 0.f);
                v2 = fmaxf(acc1[j][2], 0.f);
                v3 = fmaxf(acc1[j][3], 0.f);
            } else {
                int c0 = 8 * jj + m4;
                float2 cv0 = (g0 >= 0) ? *(const float2*)&g_cc[g0][c0] : make_float2(0.f, 0.f);
                float2 cv1 = (g1 >= 0) ? *(const float2*)&g_cc[g1][c0] : make_float2(0.f, 0.f);
                v0 = fmaxf(acc1[j][0] + cv0.x, 0.f);
                v1 = fmaxf(acc1[j][1] + cv0.y, 0.f);
                v2 = fmaxf(acc1[j][2] + cv1.x, 0.f);
                v3 = fmaxf(acc1[j][3] + cv1.y, 0.f);
            }
            ah[jj][0] = pk16(v0, v1); ah[jj][1] = pk16(v2, v3);
        }
    }

    // ---------- phase 2: two 64-col halves ----------
    #pragma unroll
    for (int h = 0; h < 2; h++) {
        float acc2[8][4];
        #pragma unroll
        for (int j = 0; j < 8; j++)
            #pragma unroll
            for (int q = 0; q < 4; q++) acc2[j][q] = 0.f;

        #pragma unroll
        for (int t = 0; t < 8; t++) {
            uint32_t A[4] = { ah[2 * t][0], ah[2 * t][1], ah[2 * t + 1][0], ah[2 * t + 1][1] };
            const uint2* wf = g_W2f + (t * 16 + h * 8) * 32 + l;
            uint2 B[8];
            #pragma unroll
            for (int j = 0; j < 8; j++) B[j] = wf[j * 32];
            #pragma unroll
            for (int j = 0; j < 8; j++) mma16816(acc2[j], A, B[j].x, B[j].y);
        }

        // epilogue 2
        if (uni) {
            #pragma unroll
            for (int j = 0; j < 8; j++) {
                int c0 = 8 * (h * 8 + j) + m4;
                float m0 = fmaxf(acc2[j][0], acc2[j][2]);
                float m1 = fmaxf(acc2[j][1], acc2[j][3]);
                #pragma unroll
                for (int d = 4; d < 32; d <<= 1) {
                    m0 = fmaxf(m0, __shfl_xor_sync(0xffffffffu, m0, d));
                    m1 = fmaxf(m1, __shfl_xor_sync(0xffffffffu, m1, d));
                }
                if (l < 4) {
                    red[wid * 128 + c0] = m0;
                    red[wid * 128 + c0 + 1] = m1;
                }
            }
        } else {
            #pragma unroll
            for (int j = 0; j < 8; j++) {
                int c0 = 8 * (h * 8 + j) + m4;
                if (g0 >= 0) {
                    atomicMaxFloat(&out[g0 * DO + c0],     acc2[j][0] + b2s[c0]);
                    atomicMaxFloat(&out[g0 * DO + c0 + 1], acc2[j][1] + b2s[c0 + 1]);
                }
                if (g1 >= 0) {
                    atomicMaxFloat(&out[g1 * DO + c0],     acc2[j][2] + b2s[c0]);
                    atomicMaxFloat(&out[g1 * DO + c0 + 1], acc2[j][3] + b2s[c0 + 1]);
                }
            }
        }
    }

    if (uni) {
        __syncthreads();
        if (tid < 128) {
            float m = red[tid];
            #pragma unroll
            for (int w = 1; w < 8; w++) m = fmaxf(m, red[w * 128 + tid]);
            atomicMaxFloat(&out[gu * DO + tid], m + b2s[tid]);
        }
    }
}

// ---------------- launch ----------------
extern "C" void kernel_launch(void* const* d_in, const int* in_sizes, int n_in,
                              void* d_out, int out_size) {
    const float* x     = (const float*)d_in[0];
    const float* pos   = (const float*)d_in[1];
    const int*   batch = (const int*)d_in[2];
    const float* lf    = (const float*)d_in[3];
    const float* W1    = (const float*)d_in[4];
    const float* b1    = (const float*)d_in[5];
    const float* W2    = (const float*)d_in[6];
    const float* b2    = (const float*)d_in[7];
    float* out = (float*)d_out;

    k_graph<<<BGR, 256>>>(x, pos, batch, lf, W1, W2, b1, out, out_size);
    int grid = (NPTS + TILE - 1) / TILE;
    k_main<<<grid, 256>>>(x, pos, batch, W1, b2, out);
}

// round 9
// speedup vs baseline: 1.0498x; 1.0427x over previous
#include <cuda_runtime.h>
#include <cuda_fp16.h>
#include <math_constants.h>
#include <limits.h>
#include <stdint.h>

#define NPTS 500000
#define BGR 64
#define DIN 64
#define DH 128
#define DO 128
#define TILE 128

// ---------------- device scratch ----------------
__device__ float g_cc[BGR][DH];
// fp16 weight fragments: [kchunk][ntile(16)][lane(32)] -> uint2 {b0,b1}
__device__ uint2 g_W1f[4 * 16 * 32];
__device__ uint2 g_W2f[8 * 16 * 32];

__device__ __forceinline__ void atomicMaxFloat(float* addr, float val) {
    if (val >= 0.0f) atomicMax((int*)addr, __float_as_int(val));
    else             atomicMin((unsigned int*)addr, __float_as_uint(val));
}

__device__ __forceinline__ uint32_t pk16(float a, float b) {
    __half2 t = __halves2half2(__float2half_rn(a), __float2half_rn(b));
    return *(uint32_t*)&t;
}

__device__ __forceinline__ void mma16816(float* c, const uint32_t* a, uint32_t b0, uint32_t b1) {
    asm volatile(
        "mma.sync.aligned.m16n8k16.row.col.f32.f16.f16.f32 "
        "{%0,%1,%2,%3}, {%4,%5,%6,%7}, {%8,%9}, {%0,%1,%2,%3};"
        : "+f"(c[0]), "+f"(c[1]), "+f"(c[2]), "+f"(c[3])
        : "r"(a[0]), "r"(a[1]), "r"(a[2]), "r"(a[3]), "r"(b0), "r"(b1));
}

// ---------------- k_graph: prep + per-graph COM/argmin/c_g/small outputs ----
__global__ __launch_bounds__(256) void k_graph(
    const float* __restrict__ x, const float* __restrict__ pos,
    const int* __restrict__ batch, const float* __restrict__ lf,
    const float* __restrict__ W1, const float* __restrict__ W2,
    const float* __restrict__ b1, float* out, int out_size) {

    const int g = blockIdx.x;
    const int tid = threadIdx.x;
    const int wid = tid >> 5, l = tid & 31;

    // ---- prep section (distributed across blocks) ----
    {
        int i = g * 256 + tid;   // 16384 threads
        int lim = (BGR * DO < out_size) ? BGR * DO : out_size;
        if (i < lim) out[i] = -CUDART_INF_F;

        if (i < 4 * 16 * 32) {   // W1x fragment: t(4), j(16), l(32)
            int ll = i & 31, t = i >> 9;
            int n = 8 * ((i >> 5) & 15) + (ll >> 2);
            int k0 = 16 * t + 2 * (ll & 3);
            uint2 v;
            v.x = pk16(W1[(DIN + k0) * DH + n],     W1[(DIN + k0 + 1) * DH + n]);
            v.y = pk16(W1[(DIN + k0 + 8) * DH + n], W1[(DIN + k0 + 9) * DH + n]);
            g_W1f[i] = v;
        }
        if (i < 8 * 16 * 32) {   // W2 fragment: t(8), j(16), l(32)
            int ll = i & 31, t = i >> 9;
            int n = 8 * ((i >> 5) & 15) + (ll >> 2);
            int k0 = 16 * t + 2 * (ll & 3);
            uint2 v;
            v.x = pk16(W2[k0 * DO + n],       W2[(k0 + 1) * DO + n]);
            v.y = pk16(W2[(k0 + 8) * DO + n], W2[(k0 + 9) * DO + n]);
            g_W2f[i] = v;
        }
    }

    __shared__ int s_s, s_e;
    __shared__ float s_red[3][8];
    __shared__ float s_com[3];
    __shared__ unsigned long long s_best;
    __shared__ int s_idx;
    __shared__ float s_x[DIN];
    __shared__ float s_p[3];

    if (tid == 0) {
        int lo = 0, hi = NPTS;
        while (lo < hi) { int m = (lo + hi) >> 1; if (batch[m] < g) lo = m + 1; else hi = m; }
        s_s = lo;
        hi = NPTS;
        while (lo < hi) { int m = (lo + hi) >> 1; if (batch[m] <= g) lo = m + 1; else hi = m; }
        s_e = lo;
        s_best = ~0ull;
    }
    __syncthreads();
    const int s = s_s, e = s_e;

    // ---- phase A: COM ----
    float sx = 0.f, sy = 0.f, sz = 0.f;
    for (int i = s + tid; i < e; i += 256) {
        sx += pos[3 * i]; sy += pos[3 * i + 1]; sz += pos[3 * i + 2];
    }
    #pragma unroll
    for (int d = 16; d >= 1; d >>= 1) {
        sx += __shfl_xor_sync(0xffffffffu, sx, d);
        sy += __shfl_xor_sync(0xffffffffu, sy, d);
        sz += __shfl_xor_sync(0xffffffffu, sz, d);
    }
    if (l == 0) { s_red[0][wid] = sx; s_red[1][wid] = sy; s_red[2][wid] = sz; }
    __syncthreads();
    if (tid < 3) {
        float t = 0.f;
        #pragma unroll
        for (int w = 0; w < 8; w++) t += s_red[tid][w];
        float cnt = (float)(e - s);
        s_com[tid] = t / fmaxf(cnt, 1.0f);
    }
    __syncthreads();

    // ---- phase B: argmin dist (first occurrence) ----
    {
        const float cx = s_com[0], cy = s_com[1], cz = s_com[2];
        unsigned long long best = ~0ull;
        for (int i = s + tid; i < e; i += 256) {
            float dx = pos[3 * i] - cx, dy = pos[3 * i + 1] - cy, dz = pos[3 * i + 2] - cz;
            float d = sqrtf(dx * dx + dy * dy + dz * dz);
            unsigned long long key = ((unsigned long long)__float_as_uint(d) << 32) | (unsigned)i;
            if (key < best) best = key;
        }
        atomicMin(&s_best, best);
    }
    __syncthreads();
    if (tid == 0)
        s_idx = (e > s) ? (int)(unsigned)(s_best & 0xffffffffu) : (NPTS - 1);
    __syncthreads();
    const int idx = s_idx;
    if (tid < DIN) s_x[tid] = x[(size_t)idx * DIN + tid];
    if (tid < 3) s_p[tid] = pos[3 * idx + tid];
    __syncthreads();

    // ---- phase C: c_g + small outputs ----
    if (tid < DH) {
        int j = tid;
        float c = b1[j];
        #pragma unroll 8
        for (int k = 0; k < DIN; k++)
            c += s_x[k] * (W1[k * DH + j] - W1[(DIN + k) * DH + j]);
        c -= s_p[0] * W1[(2 * DIN) * DH + j] + s_p[1] * W1[(2 * DIN + 1) * DH + j]
           + s_p[2] * W1[(2 * DIN + 2) * DH + j];
        g_cc[g][j] = c;
        if (j < 3)  { int o = BGR * DO + g * 3 + j;               if (o < out_size) out[o] = s_p[j]; }
        if (j == 0) { int o = BGR * DO + BGR * 3 + g;             if (o < out_size) out[o] = (float)g; }
        if (j < 9)  { int o = BGR * DO + BGR * 3 + BGR + g*9 + j; if (o < out_size) out[o] = lf[(size_t)idx * 9 + j]; }
    }
}

// ---------------- main kernel: 128 thr, 4 warps x 32 rows, 3 CTAs/SM -------
__global__ void __launch_bounds__(128, 3) k_main(
    const float* __restrict__ x, const float* __restrict__ pos,
    const int* __restrict__ batch, const float* __restrict__ W1,
    const float* __restrict__ b2, float* __restrict__ out) {

    __shared__ float wpx[128], wpy[128], wpz[128];
    __shared__ float cgs[128], b2s[128];
    __shared__ float px[128], py[128], pz[128];
    __shared__ float red[4 * 128];
    __shared__ int gbs[128];

    const int tid = threadIdx.x;
    const int wid = tid >> 5, l = tid & 31;
    const int row0 = blockIdx.x * TILE;

    {
        wpx[tid] = W1[(2 * DIN + 0) * DH + tid];
        wpy[tid] = W1[(2 * DIN + 1) * DH + tid];
        wpz[tid] = W1[(2 * DIN + 2) * DH + tid];
        b2s[tid] = b2[tid];
        int row = row0 + tid;
        if (row < NPTS) {
            px[tid] = pos[3 * row]; py[tid] = pos[3 * row + 1]; pz[tid] = pos[3 * row + 2];
            gbs[tid] = batch[row];
        } else {
            px[tid] = py[tid] = pz[tid] = 0.f;
            gbs[tid] = -1;
        }
    }
    __syncthreads();
    const int gu = gbs[0];
    const bool uni = (gu >= 0) && (gu == gbs[127]);
    cgs[tid] = (gu >= 0) ? g_cc[gu][tid] : 0.f;
    __syncthreads();

    const int q = l >> 2;
    const int m4 = 2 * (l & 3);

    // ---------- phase 1: per m-tile (2 x 16 rows), H -> fp16 A-frags ----------
    uint32_t ah[2][16][2];
    #pragma unroll
    for (int mt = 0; mt < 2; mt++) {
        const int rr0 = wid * 32 + mt * 16 + q;
        const int rr1 = rr0 + 8;
        const int r0 = row0 + rr0, r1 = row0 + rr1;

        // x fragments for this m-tile
        uint32_t xh[4][4];
        #pragma unroll
        for (int t = 0; t < 4; t++) {
            const int kb = 16 * t + m4;
            float2 x00 = make_float2(0.f, 0.f), x01 = x00, x10 = x00, x11 = x00;
            if (r0 < NPTS) {
                x00 = *(const float2*)(x + (size_t)r0 * DIN + kb);
                x01 = *(const float2*)(x + (size_t)r0 * DIN + kb + 8);
            }
            if (r1 < NPTS) {
                x10 = *(const float2*)(x + (size_t)r1 * DIN + kb);
                x11 = *(const float2*)(x + (size_t)r1 * DIN + kb + 8);
            }
            xh[t][0] = pk16(x00.x, x00.y); xh[t][1] = pk16(x10.x, x10.y);
            xh[t][2] = pk16(x01.x, x01.y); xh[t][3] = pk16(x11.x, x11.y);
        }

        const float p0x = px[rr0], p0y = py[rr0], p0z = pz[rr0];
        const float p1x = px[rr1], p1y = py[rr1], p1z = pz[rr1];
        const int g0 = gbs[rr0], g1 = gbs[rr1];

        #pragma unroll
        for (int h = 0; h < 2; h++) {
            float acc1[8][4];
            #pragma unroll
            for (int j = 0; j < 8; j++)
                #pragma unroll
                for (int qq = 0; qq < 4; qq++) acc1[j][qq] = 0.f;

            #pragma unroll
            for (int t = 0; t < 4; t++) {
                const uint2* wf = g_W1f + (t * 16 + h * 8) * 32 + l;
                uint2 B[8];
                #pragma unroll
                for (int j = 0; j < 8; j++) B[j] = wf[j * 32];
                #pragma unroll
                for (int j = 0; j < 8; j++) mma16816(acc1[j], xh[t], B[j].x, B[j].y);
            }

            // epilogue 1: + pos*Wp + c_g, relu -> fp16
            #pragma unroll
            for (int j = 0; j < 8; j++) {
                int jj = h * 8 + j;
                int c0 = 8 * jj + m4;
                float2 wx = *(float2*)&wpx[c0];
                float2 wy = *(float2*)&wpy[c0];
                float2 wz = *(float2*)&wpz[c0];
                float2 cv0, cv1;
                if (uni) {
                    cv0 = *(float2*)&cgs[c0]; cv1 = cv0;
                } else {
                    cv0 = (g0 >= 0) ? *(const float2*)&g_cc[g0][c0] : make_float2(0.f, 0.f);
                    cv1 = (g1 >= 0) ? *(const float2*)&g_cc[g1][c0] : make_float2(0.f, 0.f);
                }
                float v0 = fmaxf(acc1[j][0] + p0x * wx.x + p0y * wy.x + p0z * wz.x + cv0.x, 0.f);
                float v1 = fmaxf(acc1[j][1] + p0x * wx.y + p0y * wy.y + p0z * wz.y + cv0.y, 0.f);
                float v2 = fmaxf(acc1[j][2] + p1x * wx.x + p1y * wy.x + p1z * wz.x + cv1.x, 0.f);
                float v3 = fmaxf(acc1[j][3] + p1x * wx.y + p1y * wy.y + p1z * wz.y + cv1.y, 0.f);
                ah[mt][jj][0] = pk16(v0, v1); ah[mt][jj][1] = pk16(v2, v3);
            }
        }
    }

    // ---------- phase 2: col-quarters (4 x 32 cols), B shared across m-tiles -
    #pragma unroll
    for (int hq = 0; hq < 4; hq++) {
        float acc2[2][4][4];
        #pragma unroll
        for (int mt = 0; mt < 2; mt++)
            #pragma unroll
            for (int j = 0; j < 4; j++)
                #pragma unroll
                for (int qq = 0; qq < 4; qq++) acc2[mt][j][qq] = 0.f;

        #pragma unroll
        for (int t = 0; t < 8; t++) {
            const uint2* wf = g_W2f + (t * 16 + hq * 4) * 32 + l;
            uint2 B[4];
            #pragma unroll
            for (int j = 0; j < 4; j++) B[j] = wf[j * 32];
            #pragma unroll
            for (int mt = 0; mt < 2; mt++) {
                uint32_t A[4] = { ah[mt][2 * t][0], ah[mt][2 * t][1],
                                  ah[mt][2 * t + 1][0], ah[mt][2 * t + 1][1] };
                #pragma unroll
                for (int j = 0; j < 4; j++) mma16816(acc2[mt][j], A, B[j].x, B[j].y);
            }
        }

        // epilogue 2 for this quarter
        if (uni) {
            #pragma unroll
            for (int j = 0; j < 4; j++) {
                int c0 = 8 * (hq * 4 + j) + m4;
                float m0 = fmaxf(fmaxf(acc2[0][j][0], acc2[0][j][2]),
                                 fmaxf(acc2[1][j][0], acc2[1][j][2]));
                float m1 = fmaxf(fmaxf(acc2[0][j][1], acc2[0][j][3]),
                                 fmaxf(acc2[1][j][1], acc2[1][j][3]));
                #pragma unroll
                for (int d = 4; d < 32; d <<= 1) {
                    m0 = fmaxf(m0, __shfl_xor_sync(0xffffffffu, m0, d));
                    m1 = fmaxf(m1, __shfl_xor_sync(0xffffffffu, m1, d));
                }
                if (l < 4) {
                    red[wid * 128 + c0] = m0;
                    red[wid * 128 + c0 + 1] = m1;
                }
            }
        } else {
            #pragma unroll
            for (int mt = 0; mt < 2; mt++) {
                const int rr0 = wid * 32 + mt * 16 + q;
                const int g0 = gbs[rr0], g1 = gbs[rr0 + 8];
                #pragma unroll
                for (int j = 0; j < 4; j++) {
                    int c0 = 8 * (hq * 4 + j) + m4;
                    if (g0 >= 0) {
                        atomicMaxFloat(&out[g0 * DO + c0],     acc2[mt][j][0] + b2s[c0]);
                        atomicMaxFloat(&out[g0 * DO + c0 + 1], acc2[mt][j][1] + b2s[c0 + 1]);
                    }
                    if (g1 >= 0) {
                        atomicMaxFloat(&out[g1 * DO + c0],     acc2[mt][j][2] + b2s[c0]);
                        atomicMaxFloat(&out[g1 * DO + c0 + 1], acc2[mt][j][3] + b2s[c0 + 1]);
                    }
                }
            }
        }
    }

    if (uni) {
        __syncthreads();
        float m = red[tid];
        #pragma unroll
        for (int w = 1; w < 4; w++) m = fmaxf(m, red[w * 128 + tid]);
        atomicMaxFloat(&out[gu * DO + tid], m + b2s[tid]);
    }
}

// ---------------- launch ----------------
extern "C" void kernel_launch(void* const* d_in, const int* in_sizes, int n_in,
                              void* d_out, int out_size) {
    const float* x     = (const float*)d_in[0];
    const float* pos   = (const float*)d_in[1];
    const int*   batch = (const int*)d_in[2];
    const float* lf    = (const float*)d_in[3];
    const float* W1    = (const float*)d_in[4];
    const float* b1    = (const float*)d_in[5];
    const float* W2    = (const float*)d_in[6];
    const float* b2    = (const float*)d_in[7];
    float* out = (float*)d_out;

    k_graph<<<BGR, 256>>>(x, pos, batch, lf, W1, W2, b1, out, out_size);
    int grid = (NPTS + TILE - 1) / TILE;
    k_main<<<grid, 128>>>(x, pos, batch, W1, b2, out);
}

// round 10
// speedup vs baseline: 1.0530x; 1.0031x over previous
#include <cuda_runtime.h>
#include <cuda_fp16.h>
#include <math_constants.h>
#include <limits.h>
#include <stdint.h>

#define NPTS 500000
#define BGR 64
#define DIN 64
#define DH 128
#define DO 128
#define TILE 128

// ---------------- device scratch ----------------
__device__ float g_cc[BGR][DH];
// fp16 weight fragments: [kchunk][ntile(16)][lane(32)] -> uint2 {b0,b1}
__device__ uint2 g_W1f[4 * 16 * 32];
__device__ uint2 g_W2f[8 * 16 * 32];

__device__ __forceinline__ void atomicMaxFloat(float* addr, float val) {
    if (val >= 0.0f) atomicMax((int*)addr, __float_as_int(val));
    else             atomicMin((unsigned int*)addr, __float_as_uint(val));
}

__device__ __forceinline__ uint32_t pk16(float a, float b) {
    __half2 t = __halves2half2(__float2half_rn(a), __float2half_rn(b));
    return *(uint32_t*)&t;
}

__device__ __forceinline__ void mma16816(float* c, const uint32_t* a, uint32_t b0, uint32_t b1) {
    asm volatile(
        "mma.sync.aligned.m16n8k16.row.col.f32.f16.f16.f32 "
        "{%0,%1,%2,%3}, {%4,%5,%6,%7}, {%8,%9}, {%0,%1,%2,%3};"
        : "+f"(c[0]), "+f"(c[1]), "+f"(c[2]), "+f"(c[3])
        : "r"(a[0]), "r"(a[1]), "r"(a[2]), "r"(a[3]), "r"(b0), "r"(b1));
}

// ---------------- k_graph: prep + per-graph COM/argmin/c_g/small outputs ----
__global__ __launch_bounds__(256) void k_graph(
    const float* __restrict__ x, const float* __restrict__ pos,
    const int* __restrict__ batch, const float* __restrict__ lf,
    const float* __restrict__ W1, const float* __restrict__ W2,
    const float* __restrict__ b1, float* out, int out_size) {

    const int g = blockIdx.x;
    const int tid = threadIdx.x;
    const int wid = tid >> 5, l = tid & 31;

    // ---- prep section (distributed across blocks) ----
    {
        int i = g * 256 + tid;   // 16384 threads
        int lim = (BGR * DO < out_size) ? BGR * DO : out_size;
        if (i < lim) out[i] = -CUDART_INF_F;

        if (i < 4 * 16 * 32) {   // W1x fragment: t(4), j(16), l(32)
            int ll = i & 31, t = i >> 9;
            int n = 8 * ((i >> 5) & 15) + (ll >> 2);
            int k0 = 16 * t + 2 * (ll & 3);
            uint2 v;
            v.x = pk16(W1[(DIN + k0) * DH + n],     W1[(DIN + k0 + 1) * DH + n]);
            v.y = pk16(W1[(DIN + k0 + 8) * DH + n], W1[(DIN + k0 + 9) * DH + n]);
            g_W1f[i] = v;
        }
        if (i < 8 * 16 * 32) {   // W2 fragment: t(8), j(16), l(32)
            int ll = i & 31, t = i >> 9;
            int n = 8 * ((i >> 5) & 15) + (ll >> 2);
            int k0 = 16 * t + 2 * (ll & 3);
            uint2 v;
            v.x = pk16(W2[k0 * DO + n],       W2[(k0 + 1) * DO + n]);
            v.y = pk16(W2[(k0 + 8) * DO + n], W2[(k0 + 9) * DO + n]);
            g_W2f[i] = v;
        }
    }

    __shared__ int s_s, s_e;
    __shared__ float s_red[3][8];
    __shared__ float s_com[3];
    __shared__ unsigned long long s_best;
    __shared__ int s_idx;
    __shared__ float s_x[DIN];
    __shared__ float s_p[3];

    if (tid == 0) {
        int lo = 0, hi = NPTS;
        while (lo < hi) { int m = (lo + hi) >> 1; if (batch[m] < g) lo = m + 1; else hi = m; }
        s_s = lo;
        hi = NPTS;
        while (lo < hi) { int m = (lo + hi) >> 1; if (batch[m] <= g) lo = m + 1; else hi = m; }
        s_e = lo;
        s_best = ~0ull;
    }
    __syncthreads();
    const int s = s_s, e = s_e;

    // ---- phase A: COM ----
    float sx = 0.f, sy = 0.f, sz = 0.f;
    for (int i = s + tid; i < e; i += 256) {
        sx += pos[3 * i]; sy += pos[3 * i + 1]; sz += pos[3 * i + 2];
    }
    #pragma unroll
    for (int d = 16; d >= 1; d >>= 1) {
        sx += __shfl_xor_sync(0xffffffffu, sx, d);
        sy += __shfl_xor_sync(0xffffffffu, sy, d);
        sz += __shfl_xor_sync(0xffffffffu, sz, d);
    }
    if (l == 0) { s_red[0][wid] = sx; s_red[1][wid] = sy; s_red[2][wid] = sz; }
    __syncthreads();
    if (tid < 3) {
        float t = 0.f;
        #pragma unroll
        for (int w = 0; w < 8; w++) t += s_red[tid][w];
        float cnt = (float)(e - s);
        s_com[tid] = t / fmaxf(cnt, 1.0f);
    }
    __syncthreads();

    // ---- phase B: argmin dist (first occurrence) ----
    {
        const float cx = s_com[0], cy = s_com[1], cz = s_com[2];
        unsigned long long best = ~0ull;
        for (int i = s + tid; i < e; i += 256) {
            float dx = pos[3 * i] - cx, dy = pos[3 * i + 1] - cy, dz = pos[3 * i + 2] - cz;
            float d = sqrtf(dx * dx + dy * dy + dz * dz);
            unsigned long long key = ((unsigned long long)__float_as_uint(d) << 32) | (unsigned)i;
            if (key < best) best = key;
        }
        atomicMin(&s_best, best);
    }
    __syncthreads();
    if (tid == 0)
        s_idx = (e > s) ? (int)(unsigned)(s_best & 0xffffffffu) : (NPTS - 1);
    __syncthreads();
    const int idx = s_idx;
    if (tid < DIN) s_x[tid] = x[(size_t)idx * DIN + tid];
    if (tid < 3) s_p[tid] = pos[3 * idx + tid];
    __syncthreads();

    // ---- phase C: c_g + small outputs ----
    if (tid < DH) {
        int j = tid;
        float c = b1[j];
        #pragma unroll 8
        for (int k = 0; k < DIN; k++)
            c += s_x[k] * (W1[k * DH + j] - W1[(DIN + k) * DH + j]);
        c -= s_p[0] * W1[(2 * DIN) * DH + j] + s_p[1] * W1[(2 * DIN + 1) * DH + j]
           + s_p[2] * W1[(2 * DIN + 2) * DH + j];
        g_cc[g][j] = c;
        if (j < 3)  { int o = BGR * DO + g * 3 + j;               if (o < out_size) out[o] = s_p[j]; }
        if (j == 0) { int o = BGR * DO + BGR * 3 + g;             if (o < out_size) out[o] = (float)g; }
        if (j < 9)  { int o = BGR * DO + BGR * 3 + BGR + g*9 + j; if (o < out_size) out[o] = lf[(size_t)idx * 9 + j]; }
    }
}

// ---------------- main kernel: 128 thr, 4 warps x 32 rows, 3 CTAs/SM -------
__global__ void __launch_bounds__(128, 3) k_main(
    const float* __restrict__ x, const float* __restrict__ pos,
    const int* __restrict__ batch, const float* __restrict__ W1,
    const float* __restrict__ b2, float* __restrict__ out) {

    __shared__ float wpx[128], wpy[128], wpz[128];
    __shared__ float cgs[128], b2s[128];
    __shared__ float px[128], py[128], pz[128];
    __shared__ float red[4 * 128];
    __shared__ int gbs[128];

    const int tid = threadIdx.x;
    const int wid = tid >> 5, l = tid & 31;
    const int row0 = blockIdx.x * TILE;

    {
        wpx[tid] = W1[(2 * DIN + 0) * DH + tid];
        wpy[tid] = W1[(2 * DIN + 1) * DH + tid];
        wpz[tid] = W1[(2 * DIN + 2) * DH + tid];
        b2s[tid] = b2[tid];
        int row = row0 + tid;
        if (row < NPTS) {
            px[tid] = pos[3 * row]; py[tid] = pos[3 * row + 1]; pz[tid] = pos[3 * row + 2];
            gbs[tid] = batch[row];
        } else {
            px[tid] = py[tid] = pz[tid] = 0.f;
            gbs[tid] = -1;
        }
    }
    __syncthreads();
    const int gu = gbs[0];
    const bool uni = (gu >= 0) && (gu == gbs[127]);
    cgs[tid] = (gu >= 0) ? g_cc[gu][tid] : 0.f;
    __syncthreads();

    const int q = l >> 2;
    const int m4 = 2 * (l & 3);

    // ---------- phase 1: per m-tile (2 x 16 rows), H -> fp16 A-frags ----------
    uint32_t ah[2][16][2];
    #pragma unroll
    for (int mt = 0; mt < 2; mt++) {
        const int rr0 = wid * 32 + mt * 16 + q;
        const int rr1 = rr0 + 8;
        const int r0 = row0 + rr0, r1 = row0 + rr1;

        // x fragments for this m-tile
        uint32_t xh[4][4];
        #pragma unroll
        for (int t = 0; t < 4; t++) {
            const int kb = 16 * t + m4;
            float2 x00 = make_float2(0.f, 0.f), x01 = x00, x10 = x00, x11 = x00;
            if (r0 < NPTS) {
                x00 = *(const float2*)(x + (size_t)r0 * DIN + kb);
                x01 = *(const float2*)(x + (size_t)r0 * DIN + kb + 8);
            }
            if (r1 < NPTS) {
                x10 = *(const float2*)(x + (size_t)r1 * DIN + kb);
                x11 = *(const float2*)(x + (size_t)r1 * DIN + kb + 8);
            }
            xh[t][0] = pk16(x00.x, x00.y); xh[t][1] = pk16(x10.x, x10.y);
            xh[t][2] = pk16(x01.x, x01.y); xh[t][3] = pk16(x11.x, x11.y);
        }

        const float p0x = px[rr0], p0y = py[rr0], p0z = pz[rr0];
        const float p1x = px[rr1], p1y = py[rr1], p1z = pz[rr1];
        const int g0 = gbs[rr0], g1 = gbs[rr1];

        #pragma unroll
        for (int h = 0; h < 2; h++) {
            float acc1[8][4];
            #pragma unroll
            for (int j = 0; j < 8; j++)
                #pragma unroll
                for (int qq = 0; qq < 4; qq++) acc1[j][qq] = 0.f;

            #pragma unroll
            for (int t = 0; t < 4; t++) {
                const uint2* wf = g_W1f + (t * 16 + h * 8) * 32 + l;
                uint2 B[8];
                #pragma unroll
                for (int j = 0; j < 8; j++) B[j] = wf[j * 32];
                #pragma unroll
                for (int j = 0; j < 8; j++) mma16816(acc1[j], xh[t], B[j].x, B[j].y);
            }

            // epilogue 1: + pos*Wp + c_g, relu -> fp16
            #pragma unroll
            for (int j = 0; j < 8; j++) {
                int jj = h * 8 + j;
                int c0 = 8 * jj + m4;
                float2 wx = *(float2*)&wpx[c0];
                float2 wy = *(float2*)&wpy[c0];
                float2 wz = *(float2*)&wpz[c0];
                float2 cv0, cv1;
                if (uni) {
                    cv0 = *(float2*)&cgs[c0]; cv1 = cv0;
                } else {
                    cv0 = (g0 >= 0) ? *(const float2*)&g_cc[g0][c0] : make_float2(0.f, 0.f);
                    cv1 = (g1 >= 0) ? *(const float2*)&g_cc[g1][c0] : make_float2(0.f, 0.f);
                }
                float v0 = fmaxf(acc1[j][0] + p0x * wx.x + p0y * wy.x + p0z * wz.x + cv0.x, 0.f);
                float v1 = fmaxf(acc1[j][1] + p0x * wx.y + p0y * wy.y + p0z * wz.y + cv0.y, 0.f);
                float v2 = fmaxf(acc1[j][2] + p1x * wx.x + p1y * wy.x + p1z * wz.x + cv1.x, 0.f);
                float v3 = fmaxf(acc1[j][3] + p1x * wx.y + p1y * wy.y + p1z * wz.y + cv1.y, 0.f);
                ah[mt][jj][0] = pk16(v0, v1); ah[mt][jj][1] = pk16(v2, v3);
            }
        }
    }

    // ---------- phase 2: col-quarters (4 x 32 cols), B shared across m-tiles -
    #pragma unroll
    for (int hq = 0; hq < 4; hq++) {
        float acc2[2][4][4];
        #pragma unroll
        for (int mt = 0; mt < 2; mt++)
            #pragma unroll
            for (int j = 0; j < 4; j++)
                #pragma unroll
                for (int qq = 0; qq < 4; qq++) acc2[mt][j][qq] = 0.f;

        #pragma unroll
        for (int t = 0; t < 8; t++) {
            const uint2* wf = g_W2f + (t * 16 + hq * 4) * 32 + l;
            uint2 B[4];
            #pragma unroll
            for (int j = 0; j < 4; j++) B[j] = wf[j * 32];
            #pragma unroll
            for (int mt = 0; mt < 2; mt++) {
                uint32_t A[4] = { ah[mt][2 * t][0], ah[mt][2 * t][1],
                                  ah[mt][2 * t + 1][0], ah[mt][2 * t + 1][1] };
                #pragma unroll
                for (int j = 0; j < 4; j++) mma16816(acc2[mt][j], A, B[j].x, B[j].y);
            }
        }

        // epilogue 2 for this quarter
        if (uni) {
            #pragma unroll
            for (int j = 0; j < 4; j++) {
                int c0 = 8 * (hq * 4 + j) + m4;
                float m0 = fmaxf(fmaxf(acc2[0][j][0], acc2[0][j][2]),
                                 fmaxf(acc2[1][j][0], acc2[1][j][2]));
                float m1 = fmaxf(fmaxf(acc2[0][j][1], acc2[0][j][3]),
                                 fmaxf(acc2[1][j][1], acc2[1][j][3]));
                #pragma unroll
                for (int d = 4; d < 32; d <<= 1) {
                    m0 = fmaxf(m0, __shfl_xor_sync(0xffffffffu, m0, d));
                    m1 = fmaxf(m1, __shfl_xor_sync(0xffffffffu, m1, d));
                }
                if (l < 4) {
                    red[wid * 128 + c0] = m0;
                    red[wid * 128 + c0 + 1] = m1;
                }
            }
        } else {
            #pragma unroll
            for (int mt = 0; mt < 2; mt++) {
                const int rr0 = wid * 32 + mt * 16 + q;
                const int g0 = gbs[rr0], g1 = gbs[rr0 + 8];
                #pragma unroll
                for (int j = 0; j < 4; j++) {
                    int c0 = 8 * (hq * 4 + j) + m4;
                    if (g0 >= 0) {
                        atomicMaxFloat(&out[g0 * DO + c0],     acc2[mt][j][0] + b2s[c0]);
                        atomicMaxFloat(&out[g0 * DO + c0 + 1], acc2[mt][j][1] + b2s[c0 + 1]);
                    }
                    if (g1 >= 0) {
                        atomicMaxFloat(&out[g1 * DO + c0],     acc2[mt][j][2] + b2s[c0]);
                        atomicMaxFloat(&out[g1 * DO + c0 + 1], acc2[mt][j][3] + b2s[c0 + 1]);
                    }
                }
            }
        }
    }

    if (uni) {
        __syncthreads();
        float m = red[tid];
        #pragma unroll
        for (int w = 1; w < 4; w++) m = fmaxf(m, red[w * 128 + tid]);
        atomicMaxFloat(&out[gu * DO + tid], m + b2s[tid]);
    }
}

// ---------------- launch ----------------
extern "C" void kernel_launch(void* const* d_in, const int* in_sizes, int n_in,
                              void* d_out, int out_size) {
    const float* x     = (const float*)d_in[0];
    const float* pos   = (const float*)d_in[1];
    const int*   batch = (const int*)d_in[2];
    const float* lf    = (const float*)d_in[3];
    const float* W1    = (const float*)d_in[4];
    const float* b1    = (const float*)d_in[5];
    const float* W2    = (const float*)d_in[6];
    const float* b2    = (const float*)d_in[7];
    float* out = (float*)d_out;

    k_graph<<<BGR, 256>>>(x, pos, batch, lf, W1, W2, b1, out, out_size);
    int grid = (NPTS + TILE - 1) / TILE;
    k_main<<<grid, 128>>>(x, pos, batch, W1, b2, out);
}

// round 12
// speedup vs baseline: 1.2149x; 1.1537x over previous
#include <cuda_runtime.h>
#include <cuda_fp16.h>
#include <math_constants.h>
#include <limits.h>
#include <stdint.h>

#define NPTS 500000
#define BGR 64
#define DIN 64
#define DH 128
#define DO 128
#define TILE 128

// ---------------- device scratch ----------------
__device__ float g_cc[BGR][DH];
// paired fp16 weight fragments: uint4 = {j0.b0, j0.b1, j1.b0, j1.b1}
// layout: [kchunk][jpair][lane]
__device__ uint4 g_W1f4[4 * 8 * 32];
__device__ uint4 g_W2f4[8 * 8 * 32];

__device__ __forceinline__ void atomicMaxFloat(float* addr, float val) {
    if (val >= 0.0f) atomicMax((int*)addr, __float_as_int(val));
    else             atomicMin((unsigned int*)addr, __float_as_uint(val));
}

__device__ __forceinline__ uint32_t pk16(float a, float b) {
    __half2 t = __halves2half2(__float2half_rn(a), __float2half_rn(b));
    return *(uint32_t*)&t;
}

__device__ __forceinline__ void mma16816(float* c, const uint32_t* a, uint32_t b0, uint32_t b1) {
    asm volatile(
        "mma.sync.aligned.m16n8k16.row.col.f32.f16.f16.f32 "
        "{%0,%1,%2,%3}, {%4,%5,%6,%7}, {%8,%9}, {%0,%1,%2,%3};"
        : "+f"(c[0]), "+f"(c[1]), "+f"(c[2]), "+f"(c[3])
        : "r"(a[0]), "r"(a[1]), "r"(a[2]), "r"(a[3]), "r"(b0), "r"(b1));
}

// ---------------- k_graph: prep + per-graph COM/argmin/c_g/small outputs ----
__global__ __launch_bounds__(256) void k_graph(
    const float* __restrict__ x, const float* __restrict__ pos,
    const int* __restrict__ batch, const float* __restrict__ lf,
    const float* __restrict__ W1, const float* __restrict__ W2,
    const float* __restrict__ b1, float* out, int out_size) {

    const int g = blockIdx.x;
    const int tid = threadIdx.x;
    const int wid = tid >> 5, l = tid & 31;

    // ---- prep section (distributed across blocks) ----
    {
        int i = g * 256 + tid;   // 16384 threads
        int lim = (BGR * DO < out_size) ? BGR * DO : out_size;
        if (i < lim) out[i] = -CUDART_INF_F;

        if (i < 4 * 8 * 32) {    // W1x paired fragment: t(4), jp(8), l(32)
            int ll = i & 31, jp = (i >> 5) & 7, t = i >> 8;
            int n0 = 8 * (2 * jp)     + (ll >> 2);
            int n1 = 8 * (2 * jp + 1) + (ll >> 2);
            int k0 = 16 * t + 2 * (ll & 3);
            uint4 v;
            v.x = pk16(W1[(DIN + k0) * DH + n0],     W1[(DIN + k0 + 1) * DH + n0]);
            v.y = pk16(W1[(DIN + k0 + 8) * DH + n0], W1[(DIN + k0 + 9) * DH + n0]);
            v.z = pk16(W1[(DIN + k0) * DH + n1],     W1[(DIN + k0 + 1) * DH + n1]);
            v.w = pk16(W1[(DIN + k0 + 8) * DH + n1], W1[(DIN + k0 + 9) * DH + n1]);
            g_W1f4[i] = v;
        }
        if (i < 8 * 8 * 32) {    // W2 paired fragment: t(8), jp(8), l(32)
            int ll = i & 31, jp = (i >> 5) & 7, t = i >> 8;
            int n0 = 8 * (2 * jp)     + (ll >> 2);
            int n1 = 8 * (2 * jp + 1) + (ll >> 2);
            int k0 = 16 * t + 2 * (ll & 3);
            uint4 v;
            v.x = pk16(W2[k0 * DO + n0],       W2[(k0 + 1) * DO + n0]);
            v.y = pk16(W2[(k0 + 8) * DO + n0], W2[(k0 + 9) * DO + n0]);
            v.z = pk16(W2[k0 * DO + n1],       W2[(k0 + 1) * DO + n1]);
            v.w = pk16(W2[(k0 + 8) * DO + n1], W2[(k0 + 9) * DO + n1]);
            g_W2f4[i] = v;
        }
    }

    __shared__ int s_s, s_e;
    __shared__ float s_red[3][8];
    __shared__ float s_com[3];
    __shared__ unsigned long long s_best;
    __shared__ int s_idx;
    __shared__ float s_x[DIN];
    __shared__ float s_p[3];

    if (tid == 0) {
        int lo = 0, hi = NPTS;
        while (lo < hi) { int m = (lo + hi) >> 1; if (batch[m] < g) lo = m + 1; else hi = m; }
        s_s = lo;
        hi = NPTS;
        while (lo < hi) { int m = (lo + hi) >> 1; if (batch[m] <= g) lo = m + 1; else hi = m; }
        s_e = lo;
        s_best = ~0ull;
    }
    __syncthreads();
    const int s = s_s, e = s_e;

    // ---- phase A: COM ----
    float sx = 0.f, sy = 0.f, sz = 0.f;
    for (int i = s + tid; i < e; i += 256) {
        sx += pos[3 * i]; sy += pos[3 * i + 1]; sz += pos[3 * i + 2];
    }
    #pragma unroll
    for (int d = 16; d >= 1; d >>= 1) {
        sx += __shfl_xor_sync(0xffffffffu, sx, d);
        sy += __shfl_xor_sync(0xffffffffu, sy, d);
        sz += __shfl_xor_sync(0xffffffffu, sz, d);
    }
    if (l == 0) { s_red[0][wid] = sx; s_red[1][wid] = sy; s_red[2][wid] = sz; }
    __syncthreads();
    if (tid < 3) {
        float t = 0.f;
        #pragma unroll
        for (int w = 0; w < 8; w++) t += s_red[tid][w];
        float cnt = (float)(e - s);
        s_com[tid] = t / fmaxf(cnt, 1.0f);
    }
    __syncthreads();

    // ---- phase B: argmin dist (first occurrence) ----
    {
        const float cx = s_com[0], cy = s_com[1], cz = s_com[2];
        unsigned long long best = ~0ull;
        for (int i = s + tid; i < e; i += 256) {
            float dx = pos[3 * i] - cx, dy = pos[3 * i + 1] - cy, dz = pos[3 * i + 2] - cz;
            float d = sqrtf(dx * dx + dy * dy + dz * dz);
            unsigned long long key = ((unsigned long long)__float_as_uint(d) << 32) | (unsigned)i;
            if (key < best) best = key;
        }
        atomicMin(&s_best, best);
    }
    __syncthreads();
    if (tid == 0)
        s_idx = (e > s) ? (int)(unsigned)(s_best & 0xffffffffu) : (NPTS - 1);
    __syncthreads();
    const int idx = s_idx;
    if (tid < DIN) s_x[tid] = x[(size_t)idx * DIN + tid];
    if (tid < 3) s_p[tid] = pos[3 * idx + tid];
    __syncthreads();

    // ---- phase C: c_g + small outputs ----
    if (tid < DH) {
        int j = tid;
        float c = b1[j];
        #pragma unroll 8
        for (int k = 0; k < DIN; k++)
            c += s_x[k] * (W1[k * DH + j] - W1[(DIN + k) * DH + j]);
        c -= s_p[0] * W1[(2 * DIN) * DH + j] + s_p[1] * W1[(2 * DIN + 1) * DH + j]
           + s_p[2] * W1[(2 * DIN + 2) * DH + j];
        g_cc[g][j] = c;
        if (j < 3)  { int o = BGR * DO + g * 3 + j;               if (o < out_size) out[o] = s_p[j]; }
        if (j == 0) { int o = BGR * DO + BGR * 3 + g;             if (o < out_size) out[o] = (float)g; }
        if (j < 9)  { int o = BGR * DO + BGR * 3 + BGR + g*9 + j; if (o < out_size) out[o] = lf[(size_t)idx * 9 + j]; }
    }
}

// ---------------- main kernel: 128 thr, 4 warps x 32 rows, 3 CTAs/SM -------
__global__ void __launch_bounds__(128, 3) k_main(
    const float* __restrict__ x, const float* __restrict__ pos,
    const int* __restrict__ batch, const float* __restrict__ W1,
    const float* __restrict__ b2, float* __restrict__ out) {

    __shared__ float wpx[128], wpy[128], wpz[128];
    __shared__ float cgs[128], b2s[128];
    __shared__ float px[128], py[128], pz[128];
    __shared__ float red[4 * 128];
    __shared__ int gbs[128];

    const int tid = threadIdx.x;
    const int wid = tid >> 5, l = tid & 31;
    const int row0 = blockIdx.x * TILE;

    {
        wpx[tid] = W1[(2 * DIN + 0) * DH + tid];
        wpy[tid] = W1[(2 * DIN + 1) * DH + tid];
        wpz[tid] = W1[(2 * DIN + 2) * DH + tid];
        b2s[tid] = b2[tid];
        int row = row0 + tid;
        if (row < NPTS) {
            px[tid] = pos[3 * row]; py[tid] = pos[3 * row + 1]; pz[tid] = pos[3 * row + 2];
            gbs[tid] = batch[row];
        } else {
            px[tid] = py[tid] = pz[tid] = 0.f;
            gbs[tid] = -1;
        }
    }
    __syncthreads();
    const int gu = gbs[0];
    const bool uni = (gu >= 0) && (gu == gbs[127]);
    cgs[tid] = (gu >= 0) ? g_cc[gu][tid] : 0.f;
    __syncthreads();

    const int q = l >> 2;
    const int m4 = 2 * (l & 3);

    // ---------- load x fragments for BOTH m-tiles up front ----------
    uint32_t xh[2][4][4];
    #pragma unroll
    for (int mt = 0; mt < 2; mt++) {
        const int rr0 = wid * 32 + mt * 16 + q;
        const int r0 = row0 + rr0, r1 = r0 + 8;
        #pragma unroll
        for (int t = 0; t < 4; t++) {
            const int kb = 16 * t + m4;
            float2 x00 = make_float2(0.f, 0.f), x01 = x00, x10 = x00, x11 = x00;
            if (r0 < NPTS) {
                x00 = *(const float2*)(x + (size_t)r0 * DIN + kb);
                x01 = *(const float2*)(x + (size_t)r0 * DIN + kb + 8);
            }
            if (r1 < NPTS) {
                x10 = *(const float2*)(x + (size_t)r1 * DIN + kb);
                x11 = *(const float2*)(x + (size_t)r1 * DIN + kb + 8);
            }
            xh[mt][t][0] = pk16(x00.x, x00.y); xh[mt][t][1] = pk16(x10.x, x10.y);
            xh[mt][t][2] = pk16(x01.x, x01.y); xh[mt][t][3] = pk16(x11.x, x11.y);
        }
    }

    // ---------- phase 1: col-quarters, B loaded once, shared across m-tiles --
    uint32_t ah[2][16][2];
    #pragma unroll
    for (int hq = 0; hq < 4; hq++) {
        float acc1[2][4][4];
        #pragma unroll
        for (int mt = 0; mt < 2; mt++)
            #pragma unroll
            for (int j = 0; j < 4; j++)
                #pragma unroll
                for (int qq = 0; qq < 4; qq++) acc1[mt][j][qq] = 0.f;

        #pragma unroll
        for (int t = 0; t < 4; t++) {
            const uint4* wf = g_W1f4 + (t * 8 + hq * 2) * 32 + l;
            uint4 B0 = wf[0];
            uint4 B1 = wf[32];
            #pragma unroll
            for (int mt = 0; mt < 2; mt++) {
                mma16816(acc1[mt][0], xh[mt][t], B0.x, B0.y);
                mma16816(acc1[mt][1], xh[mt][t], B0.z, B0.w);
                mma16816(acc1[mt][2], xh[mt][t], B1.x, B1.y);
                mma16816(acc1[mt][3], xh[mt][t], B1.z, B1.w);
            }
        }

        // epilogue 1 for this quarter
        #pragma unroll
        for (int mt = 0; mt < 2; mt++) {
            const int rr0 = wid * 32 + mt * 16 + q;
            const int rr1 = rr0 + 8;
            const float p0x = px[rr0], p0y = py[rr0], p0z = pz[rr0];
            const float p1x = px[rr1], p1y = py[rr1], p1z = pz[rr1];
            const int g0 = gbs[rr0], g1 = gbs[rr1];
            #pragma unroll
            for (int j = 0; j < 4; j++) {
                int jj = hq * 4 + j;
                int c0 = 8 * jj + m4;
                float2 wx = *(float2*)&wpx[c0];
                float2 wy = *(float2*)&wpy[c0];
                float2 wz = *(float2*)&wpz[c0];
                float2 cv0, cv1;
                if (uni) {
                    cv0 = *(float2*)&cgs[c0]; cv1 = cv0;
                } else {
                    cv0 = (g0 >= 0) ? *(const float2*)&g_cc[g0][c0] : make_float2(0.f, 0.f);
                    cv1 = (g1 >= 0) ? *(const float2*)&g_cc[g1][c0] : make_float2(0.f, 0.f);
                }
                float v0 = fmaxf(acc1[mt][j][0] + p0x * wx.x + p0y * wy.x + p0z * wz.x + cv0.x, 0.f);
                float v1 = fmaxf(acc1[mt][j][1] + p0x * wx.y + p0y * wy.y + p0z * wz.y + cv0.y, 0.f);
                float v2 = fmaxf(acc1[mt][j][2] + p1x * wx.x + p1y * wy.x + p1z * wz.x + cv1.x, 0.f);
                float v3 = fmaxf(acc1[mt][j][3] + p1x * wx.y + p1y * wy.y + p1z * wz.y + cv1.y, 0.f);
                ah[mt][jj][0] = pk16(v0, v1); ah[mt][jj][1] = pk16(v2, v3);
            }
        }
    }

    // ---------- phase 2: col-quarters, B shared across m-tiles ----------
    #pragma unroll
    for (int hq = 0; hq < 4; hq++) {
        float acc2[2][4][4];
        #pragma unroll
        for (int mt = 0; mt < 2; mt++)
            #pragma unroll
            for (int j = 0; j < 4; j++)
                #pragma unroll
                for (int qq = 0; qq < 4; qq++) acc2[mt][j][qq] = 0.f;

        #pragma unroll
        for (int t = 0; t < 8; t++) {
            const uint4* wf = g_W2f4 + (t * 8 + hq * 2) * 32 + l;
            uint4 B0 = wf[0];
            uint4 B1 = wf[32];
            #pragma unroll
            for (int mt = 0; mt < 2; mt++) {
                uint32_t A[4] = { ah[mt][2 * t][0], ah[mt][2 * t][1],
                                  ah[mt][2 * t + 1][0], ah[mt][2 * t + 1][1] };
                mma16816(acc2[mt][0], A, B0.x, B0.y);
                mma16816(acc2[mt][1], A, B0.z, B0.w);
                mma16816(acc2[mt][2], A, B1.x, B1.y);
                mma16816(acc2[mt][3], A, B1.z, B1.w);
            }
        }

        // epilogue 2 for this quarter
        if (uni) {
            #pragma unroll
            for (int j = 0; j < 4; j++) {
                int c0 = 8 * (hq * 4 + j) + m4;
                float m0 = fmaxf(fmaxf(acc2[0][j][0], acc2[0][j][2]),
                                 fmaxf(acc2[1][j][0], acc2[1][j][2]));
                float m1 = fmaxf(fmaxf(acc2[0][j][1], acc2[0][j][3]),
                                 fmaxf(acc2[1][j][1], acc2[1][j][3]));
                #pragma unroll
                for (int d = 4; d < 32; d <<= 1) {
                    m0 = fmaxf(m0, __shfl_xor_sync(0xffffffffu, m0, d));
                    m1 = fmaxf(m1, __shfl_xor_sync(0xffffffffu, m1, d));
                }
                if (l < 4) {
                    red[wid * 128 + c0] = m0;
                    red[wid * 128 + c0 + 1] = m1;
                }
            }
        } else {
            #pragma unroll
            for (int mt = 0; mt < 2; mt++) {
                const int rr0 = wid * 32 + mt * 16 + q;
                const int g0 = gbs[rr0], g1 = gbs[rr0 + 8];
                #pragma unroll
                for (int j = 0; j < 4; j++) {
                    int c0 = 8 * (hq * 4 + j) + m4;
                    if (g0 >= 0) {
                        atomicMaxFloat(&out[g0 * DO + c0],     acc2[mt][j][0] + b2s[c0]);
                        atomicMaxFloat(&out[g0 * DO + c0 + 1], acc2[mt][j][1] + b2s[c0 + 1]);
                    }
                    if (g1 >= 0) {
                        atomicMaxFloat(&out[g1 * DO + c0],     acc2[mt][j][2] + b2s[c0]);
                        atomicMaxFloat(&out[g1 * DO + c0 + 1], acc2[mt][j][3] + b2s[c0 + 1]);
                    }
                }
            }
        }
    }

    if (uni) {
        __syncthreads();
        float m = red[tid];
        #pragma unroll
        for (int w = 1; w < 4; w++) m = fmaxf(m, red[w * 128 + tid]);
        atomicMaxFloat(&out[gu * DO + tid], m + b2s[tid]);
    }
}

// ---------------- launch ----------------
extern "C" void kernel_launch(void* const* d_in, const int* in_sizes, int n_in,
                              void* d_out, int out_size) {
    const float* x     = (const float*)d_in[0];
    const float* pos   = (const float*)d_in[1];
    const int*   batch = (const int*)d_in[2];
    const float* lf    = (const float*)d_in[3];
    const float* W1    = (const float*)d_in[4];
    const float* b1    = (const float*)d_in[5];
    const float* W2    = (const float*)d_in[6];
    const float* b2    = (const float*)d_in[7];
    float* out = (float*)d_out;

    k_graph<<<BGR, 256>>>(x, pos, batch, lf, W1, W2, b1, out, out_size);
    int grid = (NPTS + TILE - 1) / TILE;
    k_main<<<grid, 128>>>(x, pos, batch, W1, b2, out);
}